// round 4
// baseline (speedup 1.0000x reference)
#include <cuda_runtime.h>
#include <cuda_bf16.h>
#include <cooperative_groups.h>
#include <math.h>

namespace cg = cooperative_groups;

// Fixed problem dims
#define BB   128
#define TT   255
#define NN   256
#define HH   256
#define FH   1024
#define MM   (BB*TT)          // 32640

// Static device scratch (no allocations allowed)
__device__ float g_alpha[BB * NN];
__device__ float g_P[(size_t)MM * FH];   // 133.7 MB

// ---------------------------------------------------------------------------
// K1: alpha[b,n] = softmax_n( b_attn + sum_t X[b,t,n] * Wa[2H+t] )
// ---------------------------------------------------------------------------
__global__ __launch_bounds__(256) void k_alpha(const float* __restrict__ X,
                                               const float* __restrict__ Wa,
                                               const float* __restrict__ ba) {
    __shared__ float was[TT];
    __shared__ float red[256];
    const int b = blockIdx.x, n = threadIdx.x;
    if (n < TT) was[n] = Wa[2 * HH + n];
    __syncthreads();

    const float* xb = X + (size_t)b * TT * NN + n;
    float acc = ba[0];
#pragma unroll 5
    for (int t = 0; t < TT; ++t) acc = fmaf(xb[(size_t)t * NN], was[t], acc);

    red[n] = acc; __syncthreads();
    for (int s = 128; s > 0; s >>= 1) {
        if (n < s) red[n] = fmaxf(red[n], red[n + s]);
        __syncthreads();
    }
    const float mx = red[0]; __syncthreads();
    const float e = expf(acc - mx);
    red[n] = e; __syncthreads();
    for (int s = 128; s > 0; s >>= 1) {
        if (n < s) red[n] += red[n + s];
        __syncthreads();
    }
    g_alpha[b * NN + n] = e / red[0];
}

// ---------------------------------------------------------------------------
// K2: X_tilde = alpha * X  ->  d_out[0 : MM*NN)
// ---------------------------------------------------------------------------
__global__ __launch_bounds__(256) void k_xtilde(const float* __restrict__ X,
                                                float* __restrict__ out) {
    const int idx = blockIdx.x * 256 + threadIdx.x;          // < MM*NN/4
    const float4 x = ((const float4*)X)[idx];
    const int b   = idx / (TT * NN / 4);
    const int rem = idx - b * (TT * NN / 4);
    const int n4  = rem & (NN / 4 - 1);
    const float4 a = ((const float4*)g_alpha)[b * (NN / 4) + n4];
    float4 o;
    o.x = x.x * a.x; o.y = x.y * a.y; o.z = x.z * a.z; o.w = x.w * a.w;
    ((float4*)out)[idx] = o;
}

// ---------------------------------------------------------------------------
// K3: P = X_tilde @ W_lstm + b_lstm   (M=32640, Ncols=1024, K=256) fp32
// 128x128 tile, 256 threads, 8x8 microtile. Exact tiling, no bounds checks.
// ---------------------------------------------------------------------------
__global__ __launch_bounds__(256) void k_gemm(const float* __restrict__ A,
                                              const float* __restrict__ W,
                                              const float* __restrict__ bias) {
    __shared__ float As[16 * 132];
    __shared__ float Bs[16 * 132];
    const int tx = threadIdx.x & 15;
    const int ty = threadIdx.x >> 4;
    const int m0 = blockIdx.y * 128;
    const int c0 = blockIdx.x * 128;

    float acc[8][8];
#pragma unroll
    for (int i = 0; i < 8; ++i)
#pragma unroll
        for (int j = 0; j < 8; ++j) acc[i][j] = 0.0f;

    for (int kk0 = 0; kk0 < 256; kk0 += 16) {
#pragma unroll
        for (int i = 0; i < 2; ++i) {               // A tile (transposed in smem)
            const int id = threadIdx.x + 256 * i;
            const int q = id & 3, row = id >> 2;
            const float4 v = *(const float4*)(A + (size_t)(m0 + row) * 256 + kk0 + 4 * q);
            As[(4 * q + 0) * 132 + row] = v.x;
            As[(4 * q + 1) * 132 + row] = v.y;
            As[(4 * q + 2) * 132 + row] = v.z;
            As[(4 * q + 3) * 132 + row] = v.w;
        }
#pragma unroll
        for (int i = 0; i < 2; ++i) {               // B tile
            const int id = threadIdx.x + 256 * i;
            const int c4 = id & 31, k = id >> 5;
            *(float4*)(Bs + k * 132 + 4 * c4) =
                *(const float4*)(W + (size_t)(kk0 + k) * 1024 + c0 + 4 * c4);
        }
        __syncthreads();
#pragma unroll
        for (int kk = 0; kk < 16; ++kk) {
            const float4 a0 = *(const float4*)(As + kk * 132 + 4 * ty);
            const float4 a1 = *(const float4*)(As + kk * 132 + 64 + 4 * ty);
            const float4 b0 = *(const float4*)(Bs + kk * 132 + 4 * tx);
            const float4 b1 = *(const float4*)(Bs + kk * 132 + 64 + 4 * tx);
            const float av[8] = {a0.x, a0.y, a0.z, a0.w, a1.x, a1.y, a1.z, a1.w};
            const float bv[8] = {b0.x, b0.y, b0.z, b0.w, b1.x, b1.y, b1.z, b1.w};
#pragma unroll
            for (int i = 0; i < 8; ++i)
#pragma unroll
                for (int j = 0; j < 8; ++j) acc[i][j] = fmaf(av[i], bv[j], acc[i][j]);
        }
        __syncthreads();
    }
#pragma unroll
    for (int i = 0; i < 8; ++i) {
        const int row = (i < 4) ? (4 * ty + i) : (64 + 4 * ty + (i - 4));
        float* p = g_P + (size_t)(m0 + row) * 1024 + c0;
        float4 o0, o1;
        o0.x = acc[i][0] + bias[c0 + 4 * tx + 0];
        o0.y = acc[i][1] + bias[c0 + 4 * tx + 1];
        o0.z = acc[i][2] + bias[c0 + 4 * tx + 2];
        o0.w = acc[i][3] + bias[c0 + 4 * tx + 3];
        o1.x = acc[i][4] + bias[c0 + 64 + 4 * tx + 0];
        o1.y = acc[i][5] + bias[c0 + 64 + 4 * tx + 1];
        o1.z = acc[i][6] + bias[c0 + 64 + 4 * tx + 2];
        o1.w = acc[i][7] + bias[c0 + 64 + 4 * tx + 3];
        *(float4*)(p + 4 * tx) = o0;
        *(float4*)(p + 64 + 4 * tx) = o1;
    }
}

// ---------------------------------------------------------------------------
// K4: LSTM recurrence. 16 clusters x 8 CTAs; cluster owns 8 batches.
// CTA rank r owns hidden units j in [32r, 32r+32): gate cols g*256 + 32r + jj.
// U slice (256k x 128cols = 130KB) resident in smem. Each thread owns one
// (batch, hidden-unit) pair; c stays in a register; h exchanged via DSMEM
// double-buffered mailbox; ONE cluster.sync per step.
// ---------------------------------------------------------------------------
#define PITCH 260
#define UT_FLOATS (128 * PITCH)            // 33280
#define HB_STRIDE (8 * PITCH)              // one buffer: 8 batches x pitch
#define SMEM_FLOATS (UT_FLOATS + 2 * HB_STRIDE)
#define SMEM_BYTES (SMEM_FLOATS * 4)       // 149,760 B

__global__ __launch_bounds__(256, 1) __cluster_dims__(8, 1, 1)
void k_lstm(const float* __restrict__ X, const float* __restrict__ U,
            float* __restrict__ out_enc) {
    extern __shared__ float sm[];
    float* Ut = sm;                        // [128 cols][k pitch 260]
    float* hb = sm + UT_FLOATS;            // 2 x [8 batches][pitch 260]

    cg::cluster_group cl = cg::this_cluster();
    const int rank = (int)cl.block_rank();           // 0..7
    const int b0   = (blockIdx.x >> 3) * 8;
    const int tid  = threadIdx.x;
    const int w    = tid >> 5;
    const int lane = tid & 31;
    const int bb   = lane >> 2;                      // batch within cluster 0..7
    const int jj   = w * 4 + (lane & 3);             // hidden col within slice 0..31

    // Load U slice: Ut[(g*32+jr)*PITCH + k] = U[k*1024 + g*256 + rank*32 + jr]
    for (int idx = tid; idx < 128 * 256; idx += 256) {
        const int k = idx >> 7;
        const int cr = idx & 127;                    // cr = g*32 + jr
        const int g = cr >> 5, jr = cr & 31;
        Ut[cr * PITCH + k] = U[(size_t)k * 1024 + g * 256 + rank * 32 + jr];
    }
    // Init h0 = c0 = X[b,0,0] broadcast; fill mailbox buffer 0
    for (int idx = tid; idx < 8 * 256; idx += 256) {
        const int b = idx >> 8, k = idx & 255;
        hb[b * PITCH + k] = X[(size_t)(b0 + b) * TT * NN];
    }
    float c = X[(size_t)(b0 + bb) * TT * NN];
    cl.sync();

    const float* u0 = Ut + (jj) * PITCH;             // gate i
    const float* u1 = Ut + (32 + jj) * PITCH;        // gate f
    const float* u2 = Ut + (64 + jj) * PITCH;        // gate g
    const float* u3 = Ut + (96 + jj) * PITCH;        // gate o
    const int jglob = rank * 32 + jj;

    for (int t = 0; t < TT; ++t) {
        const float* hc = hb + (t & 1) * HB_STRIDE + bb * PITCH;
        float* hnext = hb + ((t + 1) & 1) * HB_STRIDE;

        const size_t m = (size_t)(b0 + bb) * TT + t;
        const float* pr = g_P + m * 1024 + jglob;
        const float pi = pr[0], pf = pr[256], pg = pr[512], po = pr[768];

        float ai = 0.f, af = 0.f, ag = 0.f, ao = 0.f;
#pragma unroll 8
        for (int k4 = 0; k4 < 64; ++k4) {
            const float4 hv = *(const float4*)(hc + 4 * k4);
            const float4 vi = *(const float4*)(u0 + 4 * k4);
            const float4 vf = *(const float4*)(u1 + 4 * k4);
            const float4 vg = *(const float4*)(u2 + 4 * k4);
            const float4 vo = *(const float4*)(u3 + 4 * k4);
            ai = fmaf(hv.x, vi.x, ai); ai = fmaf(hv.y, vi.y, ai);
            ai = fmaf(hv.z, vi.z, ai); ai = fmaf(hv.w, vi.w, ai);
            af = fmaf(hv.x, vf.x, af); af = fmaf(hv.y, vf.y, af);
            af = fmaf(hv.z, vf.z, af); af = fmaf(hv.w, vf.w, af);
            ag = fmaf(hv.x, vg.x, ag); ag = fmaf(hv.y, vg.y, ag);
            ag = fmaf(hv.z, vg.z, ag); ag = fmaf(hv.w, vg.w, ag);
            ao = fmaf(hv.x, vo.x, ao); ao = fmaf(hv.y, vo.y, ao);
            ao = fmaf(hv.z, vo.z, ao); ao = fmaf(hv.w, vo.w, ao);
        }
        const float gi = 1.0f / (1.0f + expf(-(pi + ai)));
        const float gf = 1.0f / (1.0f + expf(-(pf + af)));
        const float gg = tanhf(pg + ag);
        const float go = 1.0f / (1.0f + expf(-(po + ao)));
        c = gf * c + gi * gg;
        const float h = go * tanhf(c);

        out_enc[m * HH + jglob] = h;
        const int moff = bb * PITCH + jglob;
#pragma unroll
        for (int r2 = 0; r2 < 8; ++r2) {
            float* dst = cl.map_shared_rank(hnext, r2);
            dst[moff] = h;
        }
        cl.sync();
    }
}

// ---------------------------------------------------------------------------
extern "C" void kernel_launch(void* const* d_in, const int* in_sizes, int n_in,
                              void* d_out, int out_size) {
    const float* X  = (const float*)d_in[0];
    const float* Wa = (const float*)d_in[1];
    const float* ba = (const float*)d_in[2];
    const float* Wl = (const float*)d_in[3];
    const float* Ul = (const float*)d_in[4];
    const float* bl = (const float*)d_in[5];
    float* out = (float*)d_out;
    float* out_xt  = out;                          // (B,Tm1,N)
    float* out_enc = out + (size_t)MM * NN;        // (B,Tm1,H)

    cudaFuncSetAttribute(k_lstm, cudaFuncAttributeMaxDynamicSharedMemorySize,
                         SMEM_BYTES);

    k_alpha<<<BB, 256>>>(X, Wa, ba);
    k_xtilde<<<(MM * NN / 4) / 256, 256>>>(X, out_xt);
    k_gemm<<<dim3(FH / 128, MM / 128), 256>>>(out_xt, Wl, bl);
    k_lstm<<<128, 256, SMEM_BYTES>>>(X, Ul, out_enc);
}